// round 7
// baseline (speedup 1.0000x reference)
#include <cuda_runtime.h>
#include <cuda_fp16.h>
#include <cuda_bf16.h>

// Synapse_66400194396810: out[m,n] = tanh( w2 . tanh( w1 @ (A[m,n], pre[n], post[m]) + b1 ) + b2 )
// M = N = 4096, Nh = 8.
// R7: latency-exposure fix. 4 rows x 4 cols per thread: 4 independent float4 A-loads
//     (MLP_p1=4) + 8 independent acc chains per thread to fill tanh2(lat16)->HFMA2 RAW
//     bubbles. R5/R6 showed occ 44-66% is not the lever; spend regs on ILP instead.

#define NH 8
#define ROWS 4

// Half2-broadcast weight banks: [0..7]=w10, [8..15]=w11, [16..23]=w12, [24..31]=b1, [32..39]=w2, [40]=b2
__constant__ unsigned CWH[48];

__device__ __forceinline__ float htanh(float x) {
    float y;
    asm("tanh.approx.f32 %0, %1;" : "=f"(y) : "f"(x));
    return y;
}
__device__ __forceinline__ __half2 htanh2(__half2 x) {
    unsigned yi;
    asm("tanh.approx.f16x2 %0, %1;" : "=r"(yi) : "r"(*(unsigned*)&x));
    return *(__half2*)&yi;
}
__device__ __forceinline__ __half2 cwh2(int i) {
    unsigned v = CWH[i];
    return *(__half2*)&v;
}

// One-time fp32 -> half2-broadcast weight conversion, via the constant bank's global alias.
__global__ void pack_weights(const float* __restrict__ w1, const float* __restrict__ b1,
                             const float* __restrict__ w2, const float* __restrict__ b2,
                             unsigned* __restrict__ cwh) {
    const int i = threadIdx.x;
    if (i < NH) {
        __half2 h;
        h = __half2half2(__float2half_rn(w1[i * 3 + 0])); cwh[i]      = *(unsigned*)&h;
        h = __half2half2(__float2half_rn(w1[i * 3 + 1])); cwh[8 + i]  = *(unsigned*)&h;
        h = __half2half2(__float2half_rn(w1[i * 3 + 2])); cwh[16 + i] = *(unsigned*)&h;
        h = __half2half2(__float2half_rn(b1[i]));         cwh[24 + i] = *(unsigned*)&h;
        h = __half2half2(__float2half_rn(w2[i]));         cwh[32 + i] = *(unsigned*)&h;
        if (i == 0) {
            h = __half2half2(__float2half_rn(b2[0]));     cwh[40]     = *(unsigned*)&h;
        }
    }
}

__global__ void __launch_bounds__(256, 4) synapse_kernel(
    const float* __restrict__ A,
    const float* __restrict__ pre,
    const float* __restrict__ post,
    float* __restrict__ out,
    int Ncols)
{
    const int m0 = blockIdx.y * ROWS;
    const int n  = (blockIdx.x * blockDim.x + threadIdx.x) * 4;
    if (n >= Ncols) return;
    const int base = m0 * Ncols + n;

    // Front-batch all independent global loads (MLP_p1 = 4..6).
    float4 a[ROWS];
#pragma unroll
    for (int r = 0; r < ROWS; r++)
        a[r] = *reinterpret_cast<const float4*>(A + base + r * Ncols);
    const float4 p4  = *reinterpret_cast<const float4*>(pre + n);
    const float4 pq  = *reinterpret_cast<const float4*>(post + m0);  // m0 % 4 == 0

    const __half2 p2lo = __floats2half2_rn(p4.x, p4.y);
    const __half2 p2hi = __floats2half2_rn(p4.z, p4.w);
    const float pm[ROWS] = {pq.x, pq.y, pq.z, pq.w};

#pragma unroll
    for (int r = 0; r < ROWS; r++) {
        const __half2 pm2 = __float2half2_rn(pm[r]);
        const __half2 a2lo = __floats2half2_rn(a[r].x, a[r].y);
        const __half2 a2hi = __floats2half2_rn(a[r].z, a[r].w);

        __half2 acc_lo = cwh2(40);
        __half2 acc_hi = cwh2(40);
#pragma unroll
        for (int h = 0; h < NH; h++) {
            // ch = w12*post + b1 recomputed per row (cheap; keeps registers low).
            const __half2 chh = __hfma2(cwh2(16 + h), pm2, cwh2(24 + h));
            const __half2 w0 = cwh2(h), w1h = cwh2(8 + h), w2h = cwh2(32 + h);
            __half2 zlo = __hfma2(w0, a2lo, __hfma2(w1h, p2lo, chh));
            __half2 zhi = __hfma2(w0, a2hi, __hfma2(w1h, p2hi, chh));
            acc_lo = __hfma2(w2h, htanh2(zlo), acc_lo);
            acc_hi = __hfma2(w2h, htanh2(zhi), acc_hi);
        }
        const float2 flo = __half22float2(acc_lo);
        const float2 fhi = __half22float2(acc_hi);
        float4 o;
        o.x = htanh(flo.x);
        o.y = htanh(flo.y);
        o.z = htanh(fhi.x);
        o.w = htanh(fhi.y);
        *reinterpret_cast<float4*>(out + base + r * Ncols) = o;
    }
}

extern "C" void kernel_launch(void* const* d_in, const int* in_sizes, int n_in,
                              void* d_out, int out_size) {
    const float* A    = (const float*)d_in[0];
    const float* pre  = (const float*)d_in[1];
    const float* post = (const float*)d_in[2];
    const float* w1   = (const float*)d_in[3];
    const float* b1   = (const float*)d_in[4];
    const float* w2   = (const float*)d_in[5];
    const float* b2   = (const float*)d_in[6];
    float* out = (float*)d_out;

    void* cwh_alias = nullptr;
    cudaGetSymbolAddress(&cwh_alias, CWH);

    pack_weights<<<1, 32>>>(w1, b1, w2, b2, (unsigned*)cwh_alias);

    const int Ncols = in_sizes[1];        // 4096
    const int M     = out_size / Ncols;   // 4096

    dim3 block(256);
    dim3 grid((Ncols / 4 + 255) / 256, M / ROWS);  // (4, 1024)
    synapse_kernel<<<grid, block>>>(A, pre, post, out, Ncols);
}